// round 8
// baseline (speedup 1.0000x reference)
#include <cuda_runtime.h>
#include <math.h>
#include <stdint.h>

#define LL 2048
#define CCdim 2048
#define BB 4
#define DD 1024
#define ZZ 128
#define EE (2*DD+ZZ)   // 2176
#define M1 (LL*BB)     // 8192

#define STAGES 4
#define SMEM_BYTES (STAGES*2048*2*4)   // 64 KB: A + B stages

// ---------------- scratch (device globals: allocation-free) ----------------
__device__ float g_x[M1*DD];        // LN output, later h*r product
__device__ float g_u[M1*DD];        // sigmoid gate
__device__ float g_r[M1*DD];        // silu gate
__device__ float g_q[M1*ZZ];        // q (pre-scaled, tf32-rounded)
__device__ float g_k[M1*ZZ];        // k (tf32-rounded)
__device__ float g_v[M1*DD];        // silu(v) (tf32-rounded)
__device__ float g_h[M1*DD];        // attn @ v
__device__ float g_a[LL*ZZ];        // rot(alpha)
__device__ float g_b[CCdim*ZZ];     // rot(beta)
__device__ float g_bias[LL*CCdim];  // rotary relative bias
__device__ float g_qk[(size_t)BB*LL*CCdim]; // scores / attn (in place)

__device__ __forceinline__ float sigmoidf_(float v){ return 1.f/(1.f+expf(-v)); }
__device__ __forceinline__ float siluf_(float v){ return v/(1.f+expf(-v)); }

// round fp32 -> tf32 (RNA) at producers so mma truncation costs nothing extra
__device__ __forceinline__ float tfr(float x){
    uint32_t u; asm("cvt.rna.tf32.f32 %0, %1;" : "=r"(u) : "f"(x));
    return __uint_as_float(u);
}

__device__ __forceinline__ void mma8(float c[4], const uint32_t a[4], const uint32_t b[2]){
    asm volatile("mma.sync.aligned.m16n8k8.row.col.f32.tf32.tf32.f32 "
        "{%0,%1,%2,%3}, {%4,%5,%6,%7}, {%8,%9}, {%0,%1,%2,%3};\n"
        : "+f"(c[0]), "+f"(c[1]), "+f"(c[2]), "+f"(c[3])
        : "r"(a[0]), "r"(a[1]), "r"(a[2]), "r"(a[3]), "r"(b[0]), "r"(b[1]));
}

__device__ __forceinline__ void cpa16(uint32_t s, const float* g){
    asm volatile("cp.async.cg.shared.global [%0], [%1], 16;\n" :: "r"(s), "l"(g));
}
__device__ __forceinline__ void cpa_commit(){ asm volatile("cp.async.commit_group;\n"); }
template<int N>
__device__ __forceinline__ void cpa_wait(){ asm volatile("cp.async.wait_group %0;\n" :: "n"(N)); }

// ---------------- LayerNorm ----------------
__global__ void ln_kernel(const float* __restrict__ q, const float* __restrict__ w,
                          const float* __restrict__ b, float* __restrict__ x)
{
    int row = blockIdx.x;
    int tid = threadIdx.x;
    const float4* p = (const float4*)(q + (size_t)row*DD);
    float4 v = p[tid];
    float s  = v.x+v.y+v.z+v.w;
    float ss = v.x*v.x+v.y*v.y+v.z*v.z+v.w*v.w;
    #pragma unroll
    for (int o=16;o;o>>=1){ s += __shfl_xor_sync(~0u,s,o); ss += __shfl_xor_sync(~0u,ss,o); }
    __shared__ float shA[8], shB[8];
    int warp = tid>>5, lane = tid&31;
    if (lane==0){ shA[warp]=s; shB[warp]=ss; }
    __syncthreads();
    float tots=0.f, totss=0.f;
    #pragma unroll
    for (int wdx=0; wdx<8; ++wdx){ tots += shA[wdx]; totss += shB[wdx]; }
    float mean = tots*(1.f/DD);
    float var  = totss*(1.f/DD) - mean*mean;
    float rstd = rsqrtf(var + 1e-5f);
    float4 w4 = ((const float4*)w)[tid];
    float4 b4 = ((const float4*)b)[tid];
    float4 o;
    o.x = tfr((v.x-mean)*rstd*w4.x + b4.x);
    o.y = tfr((v.y-mean)*rstd*w4.y + b4.y);
    o.z = tfr((v.z-mean)*rstd*w4.z + b4.z);
    o.w = tfr((v.w-mean)*rstd*w4.w + b4.w);
    ((float4*)(x + (size_t)row*DD))[tid] = o;
}

// ---------------- rotary tables ----------------
__global__ void rotab_kernel(const float* __restrict__ alpha, const float* __restrict__ beta)
{
    int m = blockIdx.x;
    int i = threadIdx.x;
    float f = expf((float)i * (-9.210340371976184f / 64.f));
    float ang = (float)m * f;
    float s, c;
    sincosf(ang, &s, &c);
    float a1 = alpha[i], a2 = alpha[i+64];
    g_a[m*ZZ + i]      = tfr(a1*c - a2*s);
    g_a[m*ZZ + i + 64] = tfr(a2*c + a1*s);
    float b1 = beta[i],  b2 = beta[i+64];
    g_b[m*ZZ + i]      = tfr(b1*c - b2*s);
    g_b[m*ZZ + i + 64] = tfr(b2*c + b1*s);
}

// ---------------- softmax with fused rotary bias; outputs tf32-rounded ----------------
__global__ void softmax_kernel()
{
    long row = blockIdx.x;
    int  l   = (int)(row & (LL-1));
    float* p = g_qk + row * (long)CCdim;
    const float* bp = g_bias + (long)l * CCdim;
    int tid = threadIdx.x;
    float4 v0 = ((const float4*)p)[tid];
    float4 v1 = ((const float4*)p)[tid+256];
    float4 b0 = ((const float4*)bp)[tid];
    float4 b1 = ((const float4*)bp)[tid+256];
    float e0 = v0.x+b0.x, e1 = v0.y+b0.y, e2 = v0.z+b0.z, e3 = v0.w+b0.w;
    float e4 = v1.x+b1.x, e5 = v1.y+b1.y, e6 = v1.z+b1.z, e7 = v1.w+b1.w;
    float mx = fmaxf(fmaxf(fmaxf(e0,e1),fmaxf(e2,e3)), fmaxf(fmaxf(e4,e5),fmaxf(e6,e7)));
    #pragma unroll
    for (int o=16;o;o>>=1) mx = fmaxf(mx, __shfl_xor_sync(~0u,mx,o));
    __shared__ float shm[8], shs[8];
    int warp = tid>>5, lane = tid&31;
    if (lane==0) shm[warp] = mx;
    __syncthreads();
    mx = shm[0];
    #pragma unroll
    for (int wdx=1; wdx<8; ++wdx) mx = fmaxf(mx, shm[wdx]);
    e0 = expf(e0-mx); e1 = expf(e1-mx); e2 = expf(e2-mx); e3 = expf(e3-mx);
    e4 = expf(e4-mx); e5 = expf(e5-mx); e6 = expf(e6-mx); e7 = expf(e7-mx);
    float s = e0+e1+e2+e3+e4+e5+e6+e7;
    #pragma unroll
    for (int o=16;o;o>>=1) s += __shfl_xor_sync(~0u,s,o);
    if (lane==0) shs[warp] = s;
    __syncthreads();
    s = 0.f;
    #pragma unroll
    for (int wdx=0; wdx<8; ++wdx) s += shs[wdx];
    float inv = 1.f/s;
    ((float4*)p)[tid]     = make_float4(tfr(e0*inv), tfr(e1*inv), tfr(e2*inv), tfr(e3*inv));
    ((float4*)p)[tid+256] = make_float4(tfr(e4*inv), tfr(e5*inv), tfr(e6*inv), tfr(e7*inv));
}

// ---------------- h*r product (pre-pass for out projection), tf32-rounded ----------------
__global__ void hr_kernel()
{
    long i = (long)blockIdx.x*256 + threadIdx.x;
    float4 h = ((const float4*)g_h)[i];
    float4 r = ((const float4*)g_r)[i];
    ((float4*)g_x)[i] = make_float4(tfr(h.x*r.x), tfr(h.y*r.y), tfr(h.z*r.z), tfr(h.w*r.w));
}

// ---------------- TF32 GEMM, 128x128x16, 4-stage cp.async pipeline ----------------
// smem A stage: [m(128)][k(16)] rows of 64B; 16B chunk c swizzled: c ^= (m>>1)&3
// smem B stage (BT): [n(128)][k(16)] same swizzle
// smem B stage (NN): [k(16)][n(128)] rows of 512B; chunk c (0..31): c ^= (2k)&7
// All fragment LDS.32 patterns verified conflict-free (NN B needs the 2k swizzle).
template<int MODE, bool BT>
__global__ void __launch_bounds__(256, 2)
gemm_cp(const float* __restrict__ A, const float* __restrict__ Bm,
        int K, int lda, int ldb, long sAz, long sBz,
        float* __restrict__ Cout, int ldc, long sCz,
        const float* __restrict__ aux1, const float* __restrict__ aux2)
{
    extern __shared__ float smem[];
    float* As = smem;                      // STAGES * 2048
    float* Bs = smem + STAGES*2048;        // STAGES * 2048
    uint32_t AsU = (uint32_t)__cvta_generic_to_shared(As);
    uint32_t BsU = (uint32_t)__cvta_generic_to_shared(Bs);

    const int bz = blockIdx.z;
    A    += (long)bz * sAz;
    Bm   += (long)bz * sBz;
    Cout += (long)bz * sCz;

    const int m0 = blockIdx.y << 7, n0 = blockIdx.x << 7;
    const int tid = threadIdx.x, lane = tid & 31, wid = tid >> 5;
    const int wm4 = (wid >> 2) << 2;
    const int wn4 = (wid & 3) << 2;

    float acc[4][4][4];
    #pragma unroll
    for (int i=0;i<4;++i)
        #pragma unroll
        for (int j=0;j<4;++j)
            #pragma unroll
            for (int c=0;c<4;++c) acc[i][j][c] = 0.f;

    // ---- loader precompute: A (2 chunks/thread) ----
    const int ar0 = tid >> 2, ac0 = tid & 3;         // row 0..63, chunk 0..3
    const float* ga0 = A + (long)(m0 + ar0)*lda + ac0*4;
    const float* ga1 = ga0 + (long)64*lda;
    const uint32_t sa0 = (uint32_t)(ar0*16      + ((ac0 ^ ((ar0>>1)&3))<<2)) * 4;
    const uint32_t sa1 = (uint32_t)((ar0+64)*16 + ((ac0 ^ (((ar0+64)>>1)&3))<<2)) * 4;

    // ---- loader precompute: B ----
    const float *gb0, *gb1;
    uint32_t sb0, sb1;
    if (BT) {
        gb0 = Bm + (long)(n0 + ar0)*ldb + ac0*4;
        gb1 = gb0 + (long)64*ldb;
        sb0 = sa0; sb1 = sa1;
    } else {
        const int bk0 = tid >> 5, bc0 = tid & 31;    // row k 0..7, chunk 0..31
        gb0 = Bm + (long)bk0*ldb + n0 + bc0*4;
        gb1 = gb0 + (long)8*ldb;
        sb0 = (uint32_t)(bk0*128     + ((bc0 ^ ((2*bk0)&7))<<2)) * 4;
        sb1 = (uint32_t)((bk0+8)*128 + ((bc0 ^ ((2*bk0)&7))<<2)) * 4;  // (2(k+8))&7 == (2k)&7
    }

    const int ktiles = K >> 4;

    auto load_tile = [&](int slot, int kt){
        uint32_t aB = AsU + (uint32_t)slot*2048*4;
        uint32_t bB = BsU + (uint32_t)slot*2048*4;
        cpa16(aB + sa0, ga0 + kt*16);
        cpa16(aB + sa1, ga1 + kt*16);
        if (BT) {
            cpa16(bB + sb0, gb0 + kt*16);
            cpa16(bB + sb1, gb1 + kt*16);
        } else {
            cpa16(bB + sb0, gb0 + (long)kt*16*ldb);
            cpa16(bB + sb1, gb1 + (long)kt*16*ldb);
        }
    };

    auto comp = [&](int slot){
        const float* sA = As + slot*2048;
        const float* sB = Bs + slot*2048;
        #pragma unroll
        for (int ks=0; ks<2; ++ks) {
            uint32_t af[4][4], bf[4][2];
            #pragma unroll
            for (int mt=0; mt<4; ++mt) {
                int mr0 = (wm4+mt)*16 + (lane>>2);
                int mr1 = mr0 + 8;
                int s0 = (mr0>>1)&3, s1 = (mr1>>1)&3;
                const float* p0 = sA + mr0*16 + (lane&3);
                const float* p1 = sA + mr1*16 + (lane&3);
                af[mt][0] = __float_as_uint(p0[((2*ks+0)^s0)<<2]);
                af[mt][1] = __float_as_uint(p1[((2*ks+0)^s1)<<2]);
                af[mt][2] = __float_as_uint(p0[((2*ks+1)^s0)<<2]);
                af[mt][3] = __float_as_uint(p1[((2*ks+1)^s1)<<2]);
            }
            #pragma unroll
            for (int nt=0; nt<4; ++nt) {
                if (BT) {
                    int nr = (wn4+nt)*8 + (lane>>2);
                    int s = (nr>>1)&3;
                    const float* p = sB + nr*16 + (lane&3);
                    bf[nt][0] = __float_as_uint(p[((2*ks+0)^s)<<2]);
                    bf[nt][1] = __float_as_uint(p[((2*ks+1)^s)<<2]);
                } else {
                    int nn = (wn4+nt)*8 + (lane>>2);
                    int cn = nn>>2, j = nn&3;
                    int k0r = ks*8 + (lane&3);
                    int sw = (2*k0r)&7;
                    bf[nt][0] = __float_as_uint(sB[k0r*128     + ((cn^sw)<<2) + j]);
                    bf[nt][1] = __float_as_uint(sB[(k0r+4)*128 + ((cn^sw)<<2) + j]);
                }
            }
            #pragma unroll
            for (int mt=0; mt<4; ++mt)
                #pragma unroll
                for (int nt=0; nt<4; ++nt)
                    mma8(acc[mt][nt], af[mt], bf[nt]);
        }
    };

    // prologue: tiles 0..STAGES-2  (all GEMMs here have ktiles >= 8 > STAGES-1)
    #pragma unroll
    for (int s=0; s<STAGES-1; ++s) { load_tile(s, s); cpa_commit(); }

    for (int kt=0; kt<ktiles; ++kt) {
        cpa_wait<STAGES-2>();          // tile kt landed
        __syncthreads();               // everyone done with tile kt-1 (slot to be overwritten)
        int nk = kt + STAGES - 1;
        if (nk < ktiles) load_tile(nk & (STAGES-1), nk);
        cpa_commit();                  // always commit to keep group counts aligned
        comp(kt & (STAGES-1));
    }

    // ---- epilogue ----
    #pragma unroll
    for (int mt=0; mt<4; ++mt) {
        #pragma unroll
        for (int ci2=0; ci2<2; ++ci2) {
            int m = m0 + (wm4+mt)*16 + (lane>>2) + ci2*8;
            #pragma unroll
            for (int nt=0; nt<4; ++nt) {
                #pragma unroll
                for (int cj=0; cj<2; ++cj) {
                    int n = n0 + (wn4+nt)*8 + ((lane&3)<<1) + cj;
                    float v = acc[mt][nt][ci2*2+cj];
                    if (MODE==0) {
                        v += aux1[n];
                        if (n < DD)            g_u[(long)m*DD + n]        = sigmoidf_(v);
                        else if (n < 2*DD)     g_r[(long)m*DD + (n-DD)]   = siluf_(v);
                        else                   g_q[(long)m*ZZ + (n-2*DD)] = tfr(v * 0.08838834764831845f);
                    } else if (MODE==1) {
                        Cout[(long)m*ldc + n] = v;
                    } else if (MODE==2) {
                        Cout[(long)m*ldc + n] = tfr(v + aux1[n]);
                    } else if (MODE==3) {
                        Cout[(long)m*ldc + n] = tfr(siluf_(v + aux1[n]));
                    } else { // MODE 4: gated residual output
                        float t = siluf_(v + aux1[n]);
                        long idx = (long)m*DD + n;
                        float res = aux2[idx];
                        Cout[idx] = res + g_u[idx]*(t - res);
                    }
                }
            }
        }
    }
}

// ---------------- launch ----------------
extern "C" void kernel_launch(void* const* d_in, const int* in_sizes, int n_in,
                              void* d_out, int out_size)
{
    const float* query   = (const float*)d_in[0];
    const float* key_seq = (const float*)d_in[1];
    const float* value   = (const float*)d_in[2];
    const float* wq      = (const float*)d_in[3];
    const float* bq      = (const float*)d_in[4];
    const float* wk      = (const float*)d_in[5];
    const float* bk      = (const float*)d_in[6];
    const float* wv      = (const float*)d_in[7];
    const float* bv      = (const float*)d_in[8];
    const float* wh      = (const float*)d_in[9];
    const float* bh      = (const float*)d_in[10];
    const float* ln_w    = (const float*)d_in[11];
    const float* ln_b    = (const float*)d_in[12];
    const float* alpha   = (const float*)d_in[13];
    const float* beta    = (const float*)d_in[14];
    float* out = (float*)d_out;

    float *p_x, *p_q, *p_k, *p_v, *p_h, *p_a, *p_b, *p_bias, *p_qk;
    cudaGetSymbolAddress((void**)&p_x,   g_x);
    cudaGetSymbolAddress((void**)&p_q,   g_q);
    cudaGetSymbolAddress((void**)&p_k,   g_k);
    cudaGetSymbolAddress((void**)&p_v,   g_v);
    cudaGetSymbolAddress((void**)&p_h,   g_h);
    cudaGetSymbolAddress((void**)&p_a,   g_a);
    cudaGetSymbolAddress((void**)&p_b,   g_b);
    cudaGetSymbolAddress((void**)&p_bias,g_bias);
    cudaGetSymbolAddress((void**)&p_qk,  g_qk);

    static bool attr_done = false;
    if (!attr_done) {
        cudaFuncSetAttribute((const void*)gemm_cp<0,true >, cudaFuncAttributeMaxDynamicSharedMemorySize, SMEM_BYTES);
        cudaFuncSetAttribute((const void*)gemm_cp<1,true >, cudaFuncAttributeMaxDynamicSharedMemorySize, SMEM_BYTES);
        cudaFuncSetAttribute((const void*)gemm_cp<1,false>, cudaFuncAttributeMaxDynamicSharedMemorySize, SMEM_BYTES);
        cudaFuncSetAttribute((const void*)gemm_cp<2,true >, cudaFuncAttributeMaxDynamicSharedMemorySize, SMEM_BYTES);
        cudaFuncSetAttribute((const void*)gemm_cp<3,true >, cudaFuncAttributeMaxDynamicSharedMemorySize, SMEM_BYTES);
        cudaFuncSetAttribute((const void*)gemm_cp<4,true >, cudaFuncAttributeMaxDynamicSharedMemorySize, SMEM_BYTES);
        attr_done = true;
    }

    // 1. LayerNorm
    ln_kernel<<<M1, 256>>>(query, ln_w, ln_b, p_x);
    // 2. rotary a/b tables
    rotab_kernel<<<LL, 64>>>(alpha, beta);
    // 3. base projection: u / r / q  (8192 x 2176 x 1024)
    gemm_cp<0,true><<<dim3(EE/128, M1/128, 1), 256, SMEM_BYTES>>>(
        p_x, wq, DD, DD, DD, 0, 0, nullptr, 0, 0, bq, nullptr);
    // 4. k projection (8192 x 128 x 1024)
    gemm_cp<2,true><<<dim3(1, M1/128, 1), 256, SMEM_BYTES>>>(
        key_seq, wk, DD, DD, DD, 0, 0, p_k, ZZ, 0, bk, nullptr);
    // 5. v projection + silu (8192 x 1024 x 1024)
    gemm_cp<3,true><<<dim3(DD/128, M1/128, 1), 256, SMEM_BYTES>>>(
        value, wv, DD, DD, DD, 0, 0, p_v, DD, 0, bv, nullptr);
    // 6. rotary bias matrix (2048 x 2048 x 128)
    gemm_cp<1,true><<<dim3(CCdim/128, LL/128, 1), 256, SMEM_BYTES>>>(
        p_a, p_b, ZZ, ZZ, ZZ, 0, 0, p_bias, CCdim, 0, nullptr, nullptr);
    // 7. QK^T batched over B (2048 x 2048 x 128 per batch)
    gemm_cp<1,true><<<dim3(CCdim/128, LL/128, BB), 256, SMEM_BYTES>>>(
        p_q, p_k, ZZ, BB*ZZ, BB*ZZ, (long)ZZ, (long)ZZ,
        p_qk, CCdim, (long)LL*CCdim, nullptr, nullptr);
    // 8. softmax with fused bias (in place on g_qk)
    softmax_kernel<<<BB*LL, 256>>>();
    // 9. attn @ v batched (2048 x 1024 x 2048 per batch) — NN gemm
    gemm_cp<1,false><<<dim3(DD/128, LL/128, BB), 256, SMEM_BYTES>>>(
        p_qk, p_v, CCdim, CCdim, BB*DD, (long)LL*CCdim, (long)DD,
        p_h, BB*DD, (long)DD, nullptr, nullptr);
    // 9.5 h*r product into g_x (g_x free after base projection)
    hr_kernel<<<M1*DD/1024, 256>>>();
    // 10. output projection with fused silu and gated residual
    gemm_cp<4,true><<<dim3(DD/128, M1/128, 1), 256, SMEM_BYTES>>>(
        p_x, wh, DD, DD, DD, 0, 0, out, DD, 0, bh, query);
}

// round 10
// speedup vs baseline: 1.5550x; 1.5550x over previous
#include <cuda_runtime.h>
#include <cuda_fp16.h>
#include <math.h>
#include <stdint.h>

#define LL 2048
#define CCdim 2048
#define BB 4
#define DD 1024
#define ZZ 128
#define EE (2*DD+ZZ)   // 2176
#define M1 (LL*BB)     // 8192

#define STAGES 4
#define SMEM_BYTES (STAGES*2048*2*4)   // 64 KB total (A+B stages, 8KB each)

// ---------------- scratch (device globals: allocation-free) ----------------
__device__ __align__(256) __half h_x[M1*DD];          // LN output (fp16)
__device__ __align__(256) float  g_u[M1*DD];          // sigmoid gate (fp32)
__device__ __align__(256) float  g_r[M1*DD];          // silu gate (fp32)
__device__ __align__(256) __half h_q[M1*ZZ];          // q scaled (fp16)
__device__ __align__(256) __half h_k[M1*ZZ];          // k (fp16)
__device__ __align__(256) __half h_vT[(size_t)BB*DD*CCdim]; // silu(v) transposed [b][e][c]
__device__ __align__(256) float  g_h[M1*DD];          // attn @ v (fp32)
__device__ __align__(256) __half h_hx[M1*DD];         // h*r (fp16)
__device__ __align__(256) __half h_a[LL*ZZ];          // rot(alpha) fp16
__device__ __align__(256) __half h_b[CCdim*ZZ];       // rot(beta) fp16
__device__ __align__(256) float  g_bias[LL*CCdim];    // rotary bias fp32
__device__ __align__(256) float  g_qk[(size_t)BB*LL*CCdim];  // scores fp32
__device__ __align__(256) __half h_p[(size_t)BB*LL*CCdim];   // probs fp16
__device__ __align__(256) __half h_wq[EE*DD];
__device__ __align__(256) __half h_wk[ZZ*DD];
__device__ __align__(256) __half h_wv[DD*DD];
__device__ __align__(256) __half h_wh[DD*DD];
__device__ __align__(256) __half h_kin[M1*DD];        // key_seq fp16
__device__ __align__(256) __half h_vin[M1*DD];        // value fp16

__device__ __forceinline__ float sigmoidf_(float v){ return 1.f/(1.f+expf(-v)); }
__device__ __forceinline__ float siluf_(float v){ return v/(1.f+expf(-v)); }

__device__ __forceinline__ void mma16(float c[4], const uint32_t a[4], const uint32_t b[2]){
    asm volatile("mma.sync.aligned.m16n8k16.row.col.f32.f16.f16.f32 "
        "{%0,%1,%2,%3}, {%4,%5,%6,%7}, {%8,%9}, {%0,%1,%2,%3};\n"
        : "+f"(c[0]), "+f"(c[1]), "+f"(c[2]), "+f"(c[3])
        : "r"(a[0]), "r"(a[1]), "r"(a[2]), "r"(a[3]), "r"(b[0]), "r"(b[1]));
}
__device__ __forceinline__ void cpa16(uint32_t s, const __half* g){
    asm volatile("cp.async.cg.shared.global [%0], [%1], 16;\n" :: "r"(s), "l"(g));
}
__device__ __forceinline__ void cpa_commit(){ asm volatile("cp.async.commit_group;\n"); }
template<int N>
__device__ __forceinline__ void cpa_wait(){ asm volatile("cp.async.wait_group %0;\n" :: "n"(N)); }

// ---------------- fp32 -> fp16 conversion (8 elems/thread) ----------------
__global__ void f2h_kernel(const float* __restrict__ in, __half* __restrict__ out)
{
    long i = ((long)blockIdx.x*256 + threadIdx.x) * 8;
    float4 a = *(const float4*)(in + i);
    float4 b = *(const float4*)(in + i + 4);
    __half2 r[4];
    r[0] = __floats2half2_rn(a.x, a.y);
    r[1] = __floats2half2_rn(a.z, a.w);
    r[2] = __floats2half2_rn(b.x, b.y);
    r[3] = __floats2half2_rn(b.z, b.w);
    *(uint4*)(out + i) = *(uint4*)r;
}

// ---------------- LayerNorm -> fp16 ----------------
__global__ void ln_kernel(const float* __restrict__ q, const float* __restrict__ w,
                          const float* __restrict__ b, __half* __restrict__ x)
{
    int row = blockIdx.x;
    int tid = threadIdx.x;
    const float4* p = (const float4*)(q + (size_t)row*DD);
    float4 v = p[tid];
    float s  = v.x+v.y+v.z+v.w;
    float ss = v.x*v.x+v.y*v.y+v.z*v.z+v.w*v.w;
    #pragma unroll
    for (int o=16;o;o>>=1){ s += __shfl_xor_sync(~0u,s,o); ss += __shfl_xor_sync(~0u,ss,o); }
    __shared__ float shA[8], shB[8];
    int warp = tid>>5, lane = tid&31;
    if (lane==0){ shA[warp]=s; shB[warp]=ss; }
    __syncthreads();
    float tots=0.f, totss=0.f;
    #pragma unroll
    for (int wdx=0; wdx<8; ++wdx){ tots += shA[wdx]; totss += shB[wdx]; }
    float mean = tots*(1.f/DD);
    float var  = totss*(1.f/DD) - mean*mean;
    float rstd = rsqrtf(var + 1e-5f);
    float4 w4 = ((const float4*)w)[tid];
    float4 b4 = ((const float4*)b)[tid];
    __half2 o0 = __floats2half2_rn((v.x-mean)*rstd*w4.x + b4.x, (v.y-mean)*rstd*w4.y + b4.y);
    __half2 o1 = __floats2half2_rn((v.z-mean)*rstd*w4.z + b4.z, (v.w-mean)*rstd*w4.w + b4.w);
    __half2* op = (__half2*)(x + (size_t)row*DD);
    op[tid*2]   = o0;
    op[tid*2+1] = o1;
}

// ---------------- rotary tables -> fp16 ----------------
__global__ void rotab_kernel(const float* __restrict__ alpha, const float* __restrict__ beta)
{
    int m = blockIdx.x;
    int i = threadIdx.x;
    float f = expf((float)i * (-9.210340371976184f / 64.f));
    float ang = (float)m * f;
    float s, c;
    sincosf(ang, &s, &c);
    float a1 = alpha[i], a2 = alpha[i+64];
    h_a[m*ZZ + i]      = __float2half_rn(a1*c - a2*s);
    h_a[m*ZZ + i + 64] = __float2half_rn(a2*c + a1*s);
    float b1 = beta[i],  b2 = beta[i+64];
    h_b[m*ZZ + i]      = __float2half_rn(b1*c - b2*s);
    h_b[m*ZZ + i + 64] = __float2half_rn(b2*c + b1*s);
}

// ---------------- softmax (fp32 scores + fused bias) -> fp16 probs ----------------
__global__ void softmax_kernel()
{
    long row = blockIdx.x;
    int  l   = (int)(row & (LL-1));
    const float* p = g_qk + row * (long)CCdim;
    __half* hp = h_p + row * (long)CCdim;
    const float* bp = g_bias + (long)l * CCdim;
    int tid = threadIdx.x;
    float4 v0 = ((const float4*)p)[tid];
    float4 v1 = ((const float4*)p)[tid+256];
    float4 b0 = ((const float4*)bp)[tid];
    float4 b1 = ((const float4*)bp)[tid+256];
    float e0 = v0.x+b0.x, e1 = v0.y+b0.y, e2 = v0.z+b0.z, e3 = v0.w+b0.w;
    float e4 = v1.x+b1.x, e5 = v1.y+b1.y, e6 = v1.z+b1.z, e7 = v1.w+b1.w;
    float mx = fmaxf(fmaxf(fmaxf(e0,e1),fmaxf(e2,e3)), fmaxf(fmaxf(e4,e5),fmaxf(e6,e7)));
    #pragma unroll
    for (int o=16;o;o>>=1) mx = fmaxf(mx, __shfl_xor_sync(~0u,mx,o));
    __shared__ float shm[8], shs[8];
    int warp = tid>>5, lane = tid&31;
    if (lane==0) shm[warp] = mx;
    __syncthreads();
    mx = shm[0];
    #pragma unroll
    for (int wdx=1; wdx<8; ++wdx) mx = fmaxf(mx, shm[wdx]);
    e0 = expf(e0-mx); e1 = expf(e1-mx); e2 = expf(e2-mx); e3 = expf(e3-mx);
    e4 = expf(e4-mx); e5 = expf(e5-mx); e6 = expf(e6-mx); e7 = expf(e7-mx);
    float s = e0+e1+e2+e3+e4+e5+e6+e7;
    #pragma unroll
    for (int o=16;o;o>>=1) s += __shfl_xor_sync(~0u,s,o);
    if (lane==0) shs[warp] = s;
    __syncthreads();
    s = 0.f;
    #pragma unroll
    for (int wdx=0; wdx<8; ++wdx) s += shs[wdx];
    float inv = 1.f/s;
    __half2 r0[2], r1[2];
    r0[0] = __floats2half2_rn(e0*inv, e1*inv);
    r0[1] = __floats2half2_rn(e2*inv, e3*inv);
    r1[0] = __floats2half2_rn(e4*inv, e5*inv);
    r1[1] = __floats2half2_rn(e6*inv, e7*inv);
    ((uint2*)hp)[tid]     = *(uint2*)r0;
    ((uint2*)hp)[tid+256] = *(uint2*)r1;
}

// ---------------- h*r -> fp16 ----------------
__global__ void hr_kernel()
{
    long i = ((long)blockIdx.x*256 + threadIdx.x) * 4;
    float4 h = *(const float4*)(g_h + i);
    float4 r = *(const float4*)(g_r + i);
    __half2 o[2];
    o[0] = __floats2half2_rn(h.x*r.x, h.y*r.y);
    o[1] = __floats2half2_rn(h.z*r.z, h.w*r.w);
    *(uint2*)(h_hx + i) = *(uint2*)o;
}

// ---------------- FP16 tensor-core GEMM, 128x128x32, 4-stage cp.async ----------------
// smem stage: [row(128)][16 half2-units] = 64B rows; 16B chunk c swizzled c ^= (row>>1)&3.
// m16n8k16-f16 fragments in half2 units are isomorphic to m16n8k8-tf32 in float units,
// so loader/comp indexing is identical to the validated R5 kernel.
// MODE 0: base proj -> g_u/g_r/h_q.  1: fp32 store.  2: half(v+aux1[n]).
// 4: gated residual out (fp32).      5: half(silu(v+aux1[m])) (transposed V proj).
template<int MODE>
__global__ void __launch_bounds__(256, 2)
gemm_h(const __half* __restrict__ A, const __half* __restrict__ Bm,
       int K, int lda, int ldb, long sAz, long sBz,
       float* __restrict__ CF, __half* __restrict__ CH, int ldc, long sCz,
       const float* __restrict__ aux1, const float* __restrict__ aux2)
{
    extern __shared__ uint32_t smem[];
    uint32_t* As = smem;                   // STAGES * 2048 units
    uint32_t* Bs = smem + STAGES*2048;
    uint32_t AsU = (uint32_t)__cvta_generic_to_shared(As);
    uint32_t BsU = (uint32_t)__cvta_generic_to_shared(Bs);

    const int bz = blockIdx.z;
    A  += (long)bz * sAz;
    Bm += (long)bz * sBz;

    const int m0 = blockIdx.y << 7, n0 = blockIdx.x << 7;
    const int tid = threadIdx.x, lane = tid & 31, wid = tid >> 5;
    const int wm4 = (wid >> 2) << 2;
    const int wn4 = (wid & 3) << 2;

    float acc[4][4][4];
    #pragma unroll
    for (int i=0;i<4;++i)
        #pragma unroll
        for (int j=0;j<4;++j)
            #pragma unroll
            for (int c=0;c<4;++c) acc[i][j][c] = 0.f;

    // ---- loaders: 2 chunks (16B = 8 halves) per thread per operand ----
    const int ar0 = tid >> 2, ac0 = tid & 3;
    const __half* ga0 = A + (long)(m0 + ar0)*lda + ac0*8;
    const __half* ga1 = ga0 + (long)64*lda;
    const uint32_t sa0 = (uint32_t)(ar0*16      + ((ac0 ^ ((ar0>>1)&3))<<2)) * 4;
    const uint32_t sa1 = (uint32_t)((ar0+64)*16 + ((ac0 ^ (((ar0+64)>>1)&3))<<2)) * 4;
    const __half* gb0 = Bm + (long)(n0 + ar0)*ldb + ac0*8;
    const __half* gb1 = gb0 + (long)64*ldb;

    const int ktiles = K >> 5;             // KT = 32 halves

    auto load_tile = [&](int slot, int kt){
        uint32_t aB = AsU + (uint32_t)slot*2048*4;
        uint32_t bB = BsU + (uint32_t)slot*2048*4;
        cpa16(aB + sa0, ga0 + kt*32);
        cpa16(aB + sa1, ga1 + kt*32);
        cpa16(bB + sa0, gb0 + kt*32);
        cpa16(bB + sa1, gb1 + kt*32);
    };

    auto comp = [&](int slot){
        const uint32_t* sA = As + slot*2048;
        const uint32_t* sB = Bs + slot*2048;
        #pragma unroll
        for (int ks=0; ks<2; ++ks) {
            uint32_t af[4][4], bf[4][2];
            #pragma unroll
            for (int mt=0; mt<4; ++mt) {
                int mr0 = (wm4+mt)*16 + (lane>>2);
                int mr1 = mr0 + 8;
                int s0 = (mr0>>1)&3, s1 = (mr1>>1)&3;
                const uint32_t* p0 = sA + mr0*16 + (lane&3);
                const uint32_t* p1 = sA + mr1*16 + (lane&3);
                af[mt][0] = p0[((2*ks+0)^s0)<<2];
                af[mt][1] = p1[((2*ks+0)^s1)<<2];
                af[mt][2] = p0[((2*ks+1)^s0)<<2];
                af[mt][3] = p1[((2*ks+1)^s1)<<2];
            }
            #pragma unroll
            for (int nt=0; nt<4; ++nt) {
                int nr = (wn4+nt)*8 + (lane>>2);
                int s = (nr>>1)&3;
                const uint32_t* p = sB + nr*16 + (lane&3);
                bf[nt][0] = p[((2*ks+0)^s)<<2];
                bf[nt][1] = p[((2*ks+1)^s)<<2];
            }
            #pragma unroll
            for (int mt=0; mt<4; ++mt)
                #pragma unroll
                for (int nt=0; nt<4; ++nt)
                    mma16(acc[mt][nt], af[mt], bf[nt]);
        }
    };

    #pragma unroll
    for (int s=0; s<STAGES-1; ++s) { load_tile(s, s); cpa_commit(); }

    for (int kt=0; kt<ktiles; ++kt) {
        cpa_wait<STAGES-2>();
        __syncthreads();
        int nk = kt + STAGES - 1;
        if (nk < ktiles) load_tile(nk & (STAGES-1), nk);
        cpa_commit();
        comp(kt & (STAGES-1));
    }

    // ---- epilogue ----
    #pragma unroll
    for (int mt=0; mt<4; ++mt) {
        #pragma unroll
        for (int ci2=0; ci2<2; ++ci2) {
            int m = m0 + (wm4+mt)*16 + (lane>>2) + ci2*8;
            #pragma unroll
            for (int nt=0; nt<4; ++nt) {
                #pragma unroll
                for (int cj=0; cj<2; ++cj) {
                    int n = n0 + (wn4+nt)*8 + ((lane&3)<<1) + cj;
                    float v = acc[mt][nt][ci2*2+cj];
                    if (MODE==0) {
                        v += aux1[n];
                        if (n < DD)            g_u[(long)m*DD + n]        = sigmoidf_(v);
                        else if (n < 2*DD)     g_r[(long)m*DD + (n-DD)]   = siluf_(v);
                        else                   h_q[(long)m*ZZ + (n-2*DD)] = __float2half_rn(v * 0.08838834764831845f);
                    } else if (MODE==1) {
                        CF[(long)m*ldc + n + (long)bz*sCz] = v;
                    } else if (MODE==2) {
                        CH[(long)m*ldc + n + (long)bz*sCz] = __float2half_rn(v + aux1[n]);
                    } else if (MODE==5) {
                        CH[(long)m*ldc + n + (long)bz*sCz] = __float2half_rn(siluf_(v + aux1[m]));
                    } else { // MODE 4
                        float t = siluf_(v + aux1[n]);
                        long idx = (long)m*DD + n;
                        float res = aux2[idx];
                        CF[idx] = res + g_u[idx]*(t - res);
                    }
                }
            }
        }
    }
}

// ---------------- launch ----------------
extern "C" void kernel_launch(void* const* d_in, const int* in_sizes, int n_in,
                              void* d_out, int out_size)
{
    const float* query   = (const float*)d_in[0];
    const float* key_seq = (const float*)d_in[1];
    const float* value   = (const float*)d_in[2];
    const float* wq      = (const float*)d_in[3];
    const float* bq      = (const float*)d_in[4];
    const float* wk      = (const float*)d_in[5];
    const float* bk      = (const float*)d_in[6];
    const float* wv      = (const float*)d_in[7];
    const float* bv      = (const float*)d_in[8];
    const float* wh      = (const float*)d_in[9];
    const float* bh      = (const float*)d_in[10];
    const float* ln_w    = (const float*)d_in[11];
    const float* ln_b    = (const float*)d_in[12];
    const float* alpha   = (const float*)d_in[13];
    const float* beta    = (const float*)d_in[14];
    float* out = (float*)d_out;

    __half *p_wq, *p_wk, *p_wv, *p_wh, *p_kin, *p_vin, *p_x, *p_q, *p_k, *p_vT, *p_hx, *p_a, *p_b, *p_p;
    float *p_u, *p_r, *p_h, *p_bias, *p_qk;
    cudaGetSymbolAddress((void**)&p_wq,  h_wq);
    cudaGetSymbolAddress((void**)&p_wk,  h_wk);
    cudaGetSymbolAddress((void**)&p_wv,  h_wv);
    cudaGetSymbolAddress((void**)&p_wh,  h_wh);
    cudaGetSymbolAddress((void**)&p_kin, h_kin);
    cudaGetSymbolAddress((void**)&p_vin, h_vin);
    cudaGetSymbolAddress((void**)&p_x,   h_x);
    cudaGetSymbolAddress((void**)&p_q,   h_q);
    cudaGetSymbolAddress((void**)&p_k,   h_k);
    cudaGetSymbolAddress((void**)&p_vT,  h_vT);
    cudaGetSymbolAddress((void**)&p_hx,  h_hx);
    cudaGetSymbolAddress((void**)&p_a,   h_a);
    cudaGetSymbolAddress((void**)&p_b,   h_b);
    cudaGetSymbolAddress((void**)&p_p,   h_p);
    cudaGetSymbolAddress((void**)&p_u,   g_u);
    cudaGetSymbolAddress((void**)&p_r,   g_r);
    cudaGetSymbolAddress((void**)&p_h,   g_h);
    cudaGetSymbolAddress((void**)&p_bias,g_bias);
    cudaGetSymbolAddress((void**)&p_qk,  g_qk);

    static bool attr_done = false;
    if (!attr_done) {
        cudaFuncSetAttribute((const void*)gemm_h<0>, cudaFuncAttributeMaxDynamicSharedMemorySize, SMEM_BYTES);
        cudaFuncSetAttribute((const void*)gemm_h<1>, cudaFuncAttributeMaxDynamicSharedMemorySize, SMEM_BYTES);
        cudaFuncSetAttribute((const void*)gemm_h<2>, cudaFuncAttributeMaxDynamicSharedMemorySize, SMEM_BYTES);
        cudaFuncSetAttribute((const void*)gemm_h<4>, cudaFuncAttributeMaxDynamicSharedMemorySize, SMEM_BYTES);
        cudaFuncSetAttribute((const void*)gemm_h<5>, cudaFuncAttributeMaxDynamicSharedMemorySize, SMEM_BYTES);
        attr_done = true;
    }

    // 0. fp32 -> fp16 conversions (weights + GEMM-side inputs)
    f2h_kernel<<<EE*DD/2048, 256>>>(wq, p_wq);
    f2h_kernel<<<ZZ*DD/2048, 256>>>(wk, p_wk);
    f2h_kernel<<<DD*DD/2048, 256>>>(wv, p_wv);
    f2h_kernel<<<DD*DD/2048, 256>>>(wh, p_wh);
    f2h_kernel<<<M1*DD/2048, 256>>>(key_seq, p_kin);
    f2h_kernel<<<M1*DD/2048, 256>>>(value, p_vin);
    // 1. LayerNorm -> fp16
    ln_kernel<<<M1, 256>>>(query, ln_w, ln_b, p_x);
    // 2. rotary tables -> fp16
    rotab_kernel<<<LL, 64>>>(alpha, beta);
    // 3. base projection: u/r/q (8192 x 2176 x 1024)
    gemm_h<0><<<dim3(EE/128, M1/128, 1), 256, SMEM_BYTES>>>(
        p_x, p_wq, DD, DD, DD, 0, 0, nullptr, nullptr, 0, 0, bq, nullptr);
    // 4. k projection (8192 x 128 x 1024) -> h_k
    gemm_h<2><<<dim3(1, M1/128, 1), 256, SMEM_BYTES>>>(
        p_kin, p_wk, DD, DD, DD, 0, 0, nullptr, p_k, ZZ, 0, bk, nullptr);
    // 5. V projection TRANSPOSED: vT[b][e][c] = silu(wv[e,:]·value[c,b,:] + bv[e])
    gemm_h<5><<<dim3(CCdim/128, DD/128, BB), 256, SMEM_BYTES>>>(
        p_wv, p_vin, DD, DD, BB*DD, 0, (long)DD,
        nullptr, p_vT, CCdim, (long)DD*CCdim, bv, nullptr);
    // 6. rotary bias (2048 x 2048 x 128) -> fp32
    gemm_h<1><<<dim3(CCdim/128, LL/128, 1), 256, SMEM_BYTES>>>(
        p_a, p_b, ZZ, ZZ, ZZ, 0, 0, p_bias, nullptr, CCdim, 0, nullptr, nullptr);
    // 7. QK^T batched (2048 x 2048 x 128 per batch) -> fp32 scores
    gemm_h<1><<<dim3(CCdim/128, LL/128, BB), 256, SMEM_BYTES>>>(
        p_q, p_k, ZZ, BB*ZZ, BB*ZZ, (long)ZZ, (long)ZZ,
        p_qk, nullptr, CCdim, (long)LL*CCdim, nullptr, nullptr);
    // 8. softmax + fused bias -> fp16 probs
    softmax_kernel<<<BB*LL, 256>>>();
    // 9. attn @ V batched (2048 x 1024 x 2048 per batch), B = vT (K-major)
    gemm_h<1><<<dim3(DD/128, LL/128, BB), 256, SMEM_BYTES>>>(
        p_p, p_vT, CCdim, CCdim, CCdim, (long)LL*CCdim, (long)DD*CCdim,
        p_h, nullptr, BB*DD, (long)DD, nullptr, nullptr);
    // 9.5 h*r -> fp16
    hr_kernel<<<M1*DD/1024, 256>>>();
    // 10. output projection + silu + gated residual (fp32 out)
    gemm_h<4><<<dim3(DD/128, M1/128, 1), 256, SMEM_BYTES>>>(
        p_hx, p_wh, DD, DD, DD, 0, 0, out, nullptr, DD, 0, bh, query);
}